// round 2
// baseline (speedup 1.0000x reference)
#include <cuda_runtime.h>
#include <cstdint>

// Problem geometry (fixed by setup_inputs: 2048 x 2048 float32).
static constexpr int H = 2048;
static constexpr int W = 2048;
static constexpr int CHUNK = 128;          // rows per column-chunk
static constexpr int NCH = H / CHUNK;      // 16 chunks per column
static constexpr int BIGROW = 1 << 28;     // sentinel "no background row"

// Scratch (device globals — no runtime allocation allowed).
__device__ float g_f[H * W];               // squared column distance (pass-1 output)
__device__ float g_d[H * W];               // final distance (pre-normalize)
__device__ int   g_last[NCH * W];          // last bg row within chunk (or -1)
__device__ int   g_first[NCH * W];         // first bg row within chunk (or BIGROW)
__device__ int   g_lastBefore[NCH * W];    // last bg row strictly before chunk
__device__ int   g_firstAfter[NCH * W];    // first bg row strictly after chunk
__device__ unsigned int g_max_bits;        // float-bits max of g_d (all >= 0)

// ---------------------------------------------------------------------------
// K1: per (chunk, col) summary: first & last background row inside the chunk.
// Thread t -> chunk = t / W, col = t % W  (warp = 32 consecutive cols: coalesced)
// ---------------------------------------------------------------------------
__global__ void k_scan_chunks(const float* __restrict__ img) {
    int t = blockIdx.x * blockDim.x + threadIdx.x;
    if (t == 0) g_max_bits = 0u;           // reset reduction for this replay
    if (t >= NCH * W) return;
    int chunk = t / W;
    int col   = t - chunk * W;
    int base  = chunk * CHUNK;
    const float* p = img + (size_t)base * W + col;
    int last = -1, first = BIGROW;
#pragma unroll 4
    for (int r = 0; r < CHUNK; r++) {
        float v = __ldg(p + (size_t)r * W);
        if (v <= 0.5f) {                   // background pixel
            int gr = base + r;
            last = gr;
            first = min(first, gr);
        }
    }
    g_last[t]  = last;
    g_first[t] = first;
}

// ---------------------------------------------------------------------------
// K2: tiny per-column scan of the 16 chunk summaries.
// ---------------------------------------------------------------------------
__global__ void k_combine() {
    int col = blockIdx.x * blockDim.x + threadIdx.x;
    if (col >= W) return;
    int lb = -BIGROW;
    for (int k = 0; k < NCH; k++) {
        g_lastBefore[k * W + col] = lb;
        int l = g_last[k * W + col];
        if (l >= 0) lb = l;                // rows increase with k -> running max
    }
    int fa = BIGROW;
    for (int k = NCH - 1; k >= 0; k--) {
        g_firstAfter[k * W + col] = fa;
        int f0 = g_first[k * W + col];
        if (f0 < BIGROW) fa = f0;
    }
}

// ---------------------------------------------------------------------------
// K3: exact column distance per pixel inside each chunk, seeded by the
// cross-chunk summaries. Writes f = (column distance)^2 (0 for background).
// img second read mostly hits L2 (16MB tensor, ~126MB L2).
// ---------------------------------------------------------------------------
__global__ void k_column_dist(const float* __restrict__ img) {
    int t = blockIdx.x * blockDim.x + threadIdx.x;
    if (t >= NCH * W) return;
    int chunk = t / W;
    int col   = t - chunk * W;
    int base  = chunk * CHUNK;
    const float* p = img + (size_t)base * W + col;

    int last = g_lastBefore[t];
    int nxt  = g_firstAfter[t];

    int dd[CHUNK];                         // local mem, uniform index -> coalesced
#pragma unroll 4
    for (int r = 0; r < CHUNK; r++) {
        int gr = base + r;
        float v = __ldg(p + (size_t)r * W);
        if (v <= 0.5f) { last = gr; dd[r] = -1; }   // background marker
        else           { dd[r] = gr - last; }        // dist to bg above (exact)
    }
#pragma unroll 4
    for (int r = CHUNK - 1; r >= 0; r--) {
        int gr = base + r;
        float out;
        if (dd[r] < 0) { nxt = gr; out = 0.0f; }
        else {
            int d = min(dd[r], nxt - gr);
            float df = (float)d;
            out = df * df;                 // exact integer^2 in fp32
        }
        g_f[(size_t)gr * W + col] = out;
    }
}

// ---------------------------------------------------------------------------
// K4: row pass. D[j] = min_j' f[j'] + (j-j')^2 via exact outward search with
// the bound d^2 >= best (valid since f >= 0). Then d = sqrt(D), block-reduce
// max, atomicMax into g_max_bits (float bits order-preserving for >= 0).
// ---------------------------------------------------------------------------
__global__ void k_row_pass() {
    int idx = blockIdx.x * blockDim.x + threadIdx.x;
    float di = 0.0f;
    if (idx < H * W) {
        int col = idx & (W - 1);
        float best = g_f[idx];
        int maxl = col, maxr = (W - 1) - col;
        int dmax = max(maxl, maxr);
        for (int d = 1; d <= dmax; d++) {
            float fd2 = (float)(d * d);
            if (fd2 >= best) break;        // no farther candidate can win
            if (d <= maxl) best = fminf(best, __ldg(&g_f[idx - d]) + fd2);
            if (d <= maxr) best = fminf(best, __ldg(&g_f[idx + d]) + fd2);
        }
        di = __fsqrt_rn(best);
        g_d[idx] = di;
    }
    // block max reduction
    __shared__ float s[256];
    s[threadIdx.x] = di;
    __syncthreads();
    for (int off = 128; off > 0; off >>= 1) {
        if (threadIdx.x < off) s[threadIdx.x] = fmaxf(s[threadIdx.x], s[threadIdx.x + off]);
        __syncthreads();
    }
    if (threadIdx.x == 0)
        atomicMax(&g_max_bits, __float_as_uint(s[0]));
}

// ---------------------------------------------------------------------------
// K5: normalize by global max and truncate (uint8 cast in the reference is
// trunc-toward-zero; values are in [0, 255], so floorf). The harness exposes
// the uint8 output as FLOAT32 elements, so we store the integer VALUE as f32.
// ---------------------------------------------------------------------------
__global__ void k_normalize(float* __restrict__ out) {
    int idx = blockIdx.x * blockDim.x + threadIdx.x;
    if (idx >= H * W) return;
    float m = __uint_as_float(g_max_bits);
    float v = g_d[idx];
    float r = (m > 0.0f) ? (v / m * 255.0f) : v;
    out[idx] = floorf(r);                  // trunc == floor for r >= 0
}

extern "C" void kernel_launch(void* const* d_in, const int* in_sizes, int n_in,
                              void* d_out, int out_size) {
    const float* img = (const float*)d_in[0];
    float* out = (float*)d_out;
    (void)in_sizes; (void)n_in; (void)out_size;

    const int T = 256;
    k_scan_chunks<<<(NCH * W + T - 1) / T, T>>>(img);
    k_combine<<<(W + T - 1) / T, T>>>();
    k_column_dist<<<(NCH * W + T - 1) / T, T>>>(img);
    k_row_pass<<<(H * W + T - 1) / T, T>>>();
    k_normalize<<<(H * W + T - 1) / T, T>>>(out);
}

// round 3
// speedup vs baseline: 1.4138x; 1.4138x over previous
#include <cuda_runtime.h>
#include <cstdint>

// Problem geometry (fixed by setup_inputs: 2048 x 2048 float32).
static constexpr int H = 2048;
static constexpr int W = 2048;
static constexpr int NPIX = H * W;
static constexpr int TPB = 256;
static constexpr int NBLK = NPIX / TPB;    // 16384 blocks

// Scratch (device globals — no runtime allocation allowed).
__device__ float        g_d[NPIX];         // distance (pre-normalize)
__device__ unsigned int g_blockmax[NBLK];  // per-block max (float bits, all >= 0)
__device__ unsigned int g_max_bits;        // global max (float bits)

// ---------------------------------------------------------------------------
// Exact squared column distance at (row,col): distance to nearest background
// (img <= 0.5) along the column, squared. Early-exits once k^2 >= bound
// (returned value then >= bound, so the caller's fmin discards it — exact).
// Loads are warp-coalesced: a warp spans 32 consecutive cols in one row.
// ---------------------------------------------------------------------------
__device__ __forceinline__ float col_dist2(const float* __restrict__ img,
                                           int row, int col, float bound) {
    const float* p = img + col;
    if (__ldg(p + (size_t)row * W) <= 0.5f) return 0.0f;   // background pixel
    int up = row, down = (H - 1) - row;
    int kcap = max(up, down);
    for (int k = 1; k <= kcap; k++) {
        float fk2 = (float)(k * k);
        if (fk2 >= bound) return fk2;                      // cannot beat bound
        if (k <= up   && __ldg(p + (size_t)(row - k) * W) <= 0.5f) return fk2;
        if (k <= down && __ldg(p + (size_t)(row + k) * W) <= 0.5f) return fk2;
    }
    return 1.0e30f;                                        // no background in column
}

// ---------------------------------------------------------------------------
// K1: fused EDT. Per pixel: D = min over row-offsets d of
//       colDist2(row, col+d)^ + d^2
// via exact outward search with bound d^2 >= best (valid since colDist2 >= 0).
// Stores d = sqrt(D); per-block max goes to g_blockmax (no atomics).
// ---------------------------------------------------------------------------
__global__ void k_dist(const float* __restrict__ img) {
    int idx = blockIdx.x * blockDim.x + threadIdx.x;
    int col = idx & (W - 1);
    int row = idx >> 11;                                   // W == 2048

    float best = col_dist2(img, row, col, 1.0e30f);
    if (best > 0.0f) {
        int maxl = col, maxr = (W - 1) - col;
        int dmax = max(maxl, maxr);
        for (int d = 1; d <= dmax; d++) {
            float fd2 = (float)(d * d);
            if (fd2 >= best) break;                        // no farther win possible
            if (d <= maxl)
                best = fminf(best, col_dist2(img, row, col - d, best - fd2) + fd2);
            if (d <= maxr && fd2 < best)
                best = fminf(best, col_dist2(img, row, col + d, best - fd2) + fd2);
        }
    }
    float di = __fsqrt_rn(best);
    g_d[idx] = di;

    // block max (float bits preserve order for non-negative floats)
    unsigned int ib = __float_as_uint(di);
    ib = __reduce_max_sync(0xffffffffu, ib);
    __shared__ unsigned int sm[TPB / 32];
    if ((threadIdx.x & 31) == 0) sm[threadIdx.x >> 5] = ib;
    __syncthreads();
    if (threadIdx.x == 0) {
        unsigned int m = sm[0];
#pragma unroll
        for (int w = 1; w < TPB / 32; w++) m = max(m, sm[w]);
        g_blockmax[blockIdx.x] = m;
    }
}

// ---------------------------------------------------------------------------
// K2: single-block reduction of the 16384 block maxima.
// ---------------------------------------------------------------------------
__global__ void k_reduce() {
    unsigned int v = 0u;
    for (int i = threadIdx.x; i < NBLK; i += blockDim.x)
        v = max(v, g_blockmax[i]);
    v = __reduce_max_sync(0xffffffffu, v);
    __shared__ unsigned int sm[32];
    if ((threadIdx.x & 31) == 0) sm[threadIdx.x >> 5] = v;
    __syncthreads();
    if (threadIdx.x < 32) {
        unsigned int w = (threadIdx.x < (int)(blockDim.x >> 5)) ? sm[threadIdx.x] : 0u;
        w = __reduce_max_sync(0xffffffffu, w);
        if (threadIdx.x == 0) g_max_bits = w;
    }
}

// ---------------------------------------------------------------------------
// K3: normalize by global max, truncate toward zero (uint8 cast semantics;
// values in [0,255] so floorf). Harness exposes the output as float32.
// float4-vectorized: 1M threads.
// ---------------------------------------------------------------------------
__global__ void k_normalize(float* __restrict__ out) {
    int idx = blockIdx.x * blockDim.x + threadIdx.x;
    if (idx >= NPIX / 4) return;
    float m = __uint_as_float(g_max_bits);
    float4 v = reinterpret_cast<const float4*>(g_d)[idx];
    float4 r;
    if (m > 0.0f) {
        r.x = floorf(v.x / m * 255.0f);
        r.y = floorf(v.y / m * 255.0f);
        r.z = floorf(v.z / m * 255.0f);
        r.w = floorf(v.w / m * 255.0f);
    } else {
        r.x = floorf(v.x); r.y = floorf(v.y); r.z = floorf(v.z); r.w = floorf(v.w);
    }
    reinterpret_cast<float4*>(out)[idx] = r;
}

extern "C" void kernel_launch(void* const* d_in, const int* in_sizes, int n_in,
                              void* d_out, int out_size) {
    const float* img = (const float*)d_in[0];
    float* out = (float*)d_out;
    (void)in_sizes; (void)n_in; (void)out_size;

    k_dist<<<NBLK, TPB>>>(img);
    k_reduce<<<1, 1024>>>();
    k_normalize<<<(NPIX / 4 + TPB - 1) / TPB, TPB>>>(out);
}